// round 5
// baseline (speedup 1.0000x reference)
#include <cuda_runtime.h>

typedef unsigned long long u64;
typedef unsigned int u32;

#define BD   32
#define LD   513
#define DD   8
#define HD   64
#define WINW 16
#define NW   32
#define OUTD 4
#define NPAIR 28
#define NTH  512

// ---- smem layout (float offsets) ----
#define OFF_W1Q  0        // ulonglong2[16*128] fp32 quads: W1Q[b4*128+r] = W1[r][4b4..+3]
#define OFF_W2B  8192     // uint4[16*128] bf16: W2B[r8*128+k] = bf16(W2[k][8r8..+7])
#define OFF_W3B  16384    // uint4[16*512] bf16: W3B[q8*512+row] = bf16(W3[row][8q8..+7])
#define OFF_G    49152    // 1152
#define OFF_Y    50304
#define OFF_YMID 50368
#define OFF_K1   50432
#define OFF_CM   50496
#define OFF_H1   50560
#define OFF_S1   50688
#define OFF_H2   50816
#define OFF_S2   50944
#define OFF_F    51072    // 512
#define OFF_VPT  51584    // 512 (aliased by sp: VpT dead after U1', sp born in diag)
#define OFF_SP   51584
#define OFF_D1F  52096    // 1024
#define OFF_EF   53120    // 1024
#define OFF_B1   54144
#define OFF_B2   54272
#define OFF_B3   54400    // 512
#define OFF_WR   54912    // 256
#define OFF_BR   55168
#define OFF_SHIFT 55172
#define OFF_RO   55176    // 8
#define SMEM_FLOATS 55184 // 220,736 B

__device__ const signed char PI_[NPAIR] = {0,0,0,0,0,0,0, 1,1,1,1,1,1, 2,2,2,2,2, 3,3,3,3, 4,4,4, 5,5, 6};
__device__ const signed char PJ_[NPAIR] = {1,2,3,4,5,6,7, 2,3,4,5,6,7, 3,4,5,6,7, 4,5,6,7, 5,6,7, 6,7, 7};

// ---------- fast math ----------
__device__ __forceinline__ float ex2f(float x){ float y; asm("ex2.approx.f32 %0, %1;" : "=f"(y) : "f"(x)); return y; }
__device__ __forceinline__ float rcpf(float x){ float y; asm("rcp.approx.f32 %0, %1;" : "=f"(y) : "f"(x)); return y; }
__device__ __forceinline__ float sigf(float x){ return rcpf(1.0f + ex2f(-1.4426950408889634f * x)); }
__device__ __forceinline__ float tanh_fast(float x){
    float t = ex2f(2.8853900817779268f * x);
    return 1.0f - 2.0f * rcpf(t + 1.0f);
}
__device__ __forceinline__ float lipswish(float x, float* dout){
    float s = sigf(x);
    *dout = 0.909f * s * fmaf(x, 1.0f - s, 1.0f);
    return 0.909f * x * s;
}

// ---------- packed f32x2 ----------
__device__ __forceinline__ u64 f2u(float x, float y){ u64 v; asm("mov.b64 %0, {%1, %2};" : "=l"(v) : "f"(x), "f"(y)); return v; }
__device__ __forceinline__ float hsum2(u64 v){ float a, b; asm("mov.b64 {%0, %1}, %2;" : "=f"(a), "=f"(b) : "l"(v)); return a + b; }
__device__ __forceinline__ u64 fma2(u64 a, u64 b, u64 c){ u64 d; asm("fma.rn.f32x2 %0, %1, %2, %3;" : "=l"(d) : "l"(a), "l"(b), "l"(c)); return d; }

// ---------- bf16 ----------
__device__ __forceinline__ u32 pk_bf16(float lo, float hi){
    u32 r; asm("cvt.rn.bf16x2.f32 %0, %1, %2;" : "=r"(r) : "f"(hi), "f"(lo)); return r;
}
__device__ __forceinline__ float lo2f(u32 w){ return __uint_as_float(w << 16); }
__device__ __forceinline__ float hi2f(u32 w){ return __uint_as_float(w & 0xffff0000u); }

// 8 bf16 weights (uint4) dot 8 fp32 (two float4) into two accumulators
__device__ __forceinline__ void bf8_fma(float& a0, float& a1, uint4 w, float4 ha, float4 hb){
    a0 = fmaf(lo2f(w.x), ha.x, a0); a1 = fmaf(hi2f(w.x), ha.y, a1);
    a0 = fmaf(lo2f(w.y), ha.z, a0); a1 = fmaf(hi2f(w.y), ha.w, a1);
    a0 = fmaf(lo2f(w.z), hb.x, a0); a1 = fmaf(hi2f(w.z), hb.y, a1);
    a0 = fmaf(lo2f(w.w), hb.z, a0); a1 = fmaf(hi2f(w.w), hb.w, a1);
}

__device__ __forceinline__ int pidx(int i, int j) { return (i * (13 - i)) / 2 + j - 1; }

extern __shared__ float sm[];

// Readout partials of y (tid<64 callers only): sRO[w*4+o] = partial Wr[o].y
__device__ __forceinline__ void readout_partial(int tid, float yval){
    const int lane = tid & 31, w = tid >> 5;
    #pragma unroll
    for (int o = 0; o < 4; o++){
        float v = sm[OFF_WR + o * 64 + tid] * yval;
        v += __shfl_xor_sync(0xffffffffu, v, 16);
        v += __shfl_xor_sync(0xffffffffu, v, 8);
        v += __shfl_xor_sync(0xffffffffu, v, 4);
        v += __shfl_xor_sync(0xffffffffu, v, 2);
        v += __shfl_xor_sync(0xffffffffu, v, 1);
        if (lane == 0) sm[OFF_RO + w * 4 + o] = v;
    }
}

// PH=1: writes sk1, symid.  PH=2: updates sy, computes readout partials.
template<int PH>
__device__ __forceinline__ void vf_apply(int tid, const float* __restrict__ yv,
                                         const float* __restrict__ gvec, float dt)
{
    const ulonglong2* W1Q = (const ulonglong2*)(sm + OFF_W1Q);
    const uint4* W2B = (const uint4*)(sm + OFF_W2B);
    const uint4* W3B = (const uint4*)(sm + OFF_W3B);
    float* sh1 = sm + OFF_H1;  float* ss1 = sm + OFF_S1;
    float* sh2 = sm + OFF_H2;  float* ss2 = sm + OFF_S2;
    float* sf  = sm + OFF_F;
    float* sVpT = sm + OFF_VPT; float* sD1F = sm + OFF_D1F;
    float* sEF = sm + OFF_EF;  float* sp = sm + OFF_SP;
    const float* scm = sm + OFF_CM;

    const int r128 = tid >> 2, c = tid & 3;

    // ---- P1: L1 forward (fp32 W1, all 512 threads, shfl-reduce over c) ----
    {
        u64 a0 = 0ull, a1 = 0ull;
        #pragma unroll
        for (int ib = 0; ib < 4; ib++){
            const int b4 = c * 4 + ib;
            ulonglong2 w = W1Q[b4 * 128 + r128];
            ulonglong2 yq = *(const ulonglong2*)(yv + 4 * b4);
            a0 = fma2(w.x, yq.x, a0);
            a1 = fma2(w.y, yq.y, a1);
        }
        float s = hsum2(a0) + hsum2(a1);
        s += __shfl_xor_sync(0xffffffffu, s, 1);
        s += __shfl_xor_sync(0xffffffffu, s, 2);
        if (c == 0){
            float d; sh1[r128] = lipswish(s + sm[OFF_B1 + r128], &d); ss1[r128] = d;
        }
    }
    __syncthreads();

    // ---- P2: L2 forward (bf16 W2) ----
    {
        float a0 = 0.f, a1 = 0.f;
        #pragma unroll
        for (int i = 0; i < 4; i++){
            const int r8 = c * 4 + i;
            uint4 w = W2B[r8 * 128 + r128];
            float4 ha = *(const float4*)(sh1 + 8 * r8);
            float4 hb = *(const float4*)(sh1 + 8 * r8 + 4);
            bf8_fma(a0, a1, w, ha, hb);
        }
        float s = a0 + a1;
        s += __shfl_xor_sync(0xffffffffu, s, 1);
        s += __shfl_xor_sync(0xffffffffu, s, 2);
        if (c == 0){
            float d; sh2[r128] = lipswish(s + sm[OFF_B2 + r128], &d); ss2[r128] = d;
        }
    }
    __syncthreads();

    // ---- P3: L3 forward (bf16 W3, full K=128, row = tid) ----
    {
        const int row = tid;
        float a0 = 0.f, a1 = 0.f;
        #pragma unroll 4
        for (int q8 = 0; q8 < 16; q8++){
            uint4 w = W3B[q8 * 512 + row];
            float4 ha = *(const float4*)(sh2 + 8 * q8);
            float4 hb = *(const float4*)(sh2 + 8 * q8 + 4);
            bf8_fma(a0, a1, w, ha, hb);
        }
        sf[row] = tanh_fast(sm[OFF_B3 + row] + a0 + a1);
    }
    __syncthreads();

    // ---- P4: VpT[j][b] = sum_i f[i*64+b] * cmat[i][j] ----
    {
        const int j = tid >> 6, bq = tid & 63;
        float acc = 0.f;
        #pragma unroll
        for (int i = 0; i < 8; i++) acc += sf[i * 64 + bq] * scm[i * 8 + j];
        sVpT[j * 64 + bq] = acc;
    }
    __syncthreads();

    // ---- P5: U1' (fp32 W1): D1F[j][r] = ss1[r] * (W1[r,:] . VpT[j,:]) ----
    {
        u64 acc[8] = {0ull,0ull,0ull,0ull,0ull,0ull,0ull,0ull};
        #pragma unroll
        for (int ib = 0; ib < 4; ib++){
            const int b4 = c * 4 + ib;
            ulonglong2 w = W1Q[b4 * 128 + r128];
            #pragma unroll
            for (int j = 0; j < 8; j++){
                ulonglong2 d = *(const ulonglong2*)(sVpT + j * 64 + 4 * b4);
                acc[j] = fma2(w.x, d.x, acc[j]);
                acc[j] = fma2(w.y, d.y, acc[j]);
            }
        }
        float v[8];
        #pragma unroll
        for (int j = 0; j < 8; j++) v[j] = hsum2(acc[j]);
        #pragma unroll
        for (int j = 0; j < 8; j++){
            v[j] += __shfl_xor_sync(0xffffffffu, v[j], 1);
            v[j] += __shfl_xor_sync(0xffffffffu, v[j], 2);
        }
        if (c == 0){
            const float s = ss1[r128];
            #pragma unroll
            for (int j = 0; j < 8; j++) sD1F[j * 128 + r128] = s * v[j];
        }
    }
    __syncthreads();

    // ---- P6: U2' (bf16 W2): EF[j][k] = ss2[k] * (W2[k,:] . D1F[j,:]) ----
    {
        float acc[8] = {0,0,0,0,0,0,0,0};
        #pragma unroll
        for (int i = 0; i < 4; i++){
            const int r8 = c * 4 + i;
            uint4 w = W2B[r8 * 128 + r128];
            float w0 = lo2f(w.x), w1 = hi2f(w.x), w2 = lo2f(w.y), w3 = hi2f(w.y);
            float w4 = lo2f(w.z), w5 = hi2f(w.z), w6 = lo2f(w.w), w7 = hi2f(w.w);
            #pragma unroll
            for (int j = 0; j < 8; j++){
                float4 d0 = *(const float4*)(sD1F + j * 128 + 8 * r8);
                float4 d1 = *(const float4*)(sD1F + j * 128 + 8 * r8 + 4);
                float t = acc[j];
                t = fmaf(w0, d0.x, t); t = fmaf(w1, d0.y, t);
                t = fmaf(w2, d0.z, t); t = fmaf(w3, d0.w, t);
                t = fmaf(w4, d1.x, t); t = fmaf(w5, d1.y, t);
                t = fmaf(w6, d1.z, t); t = fmaf(w7, d1.w, t);
                acc[j] = t;
            }
        }
        #pragma unroll
        for (int j = 0; j < 8; j++){
            acc[j] += __shfl_xor_sync(0xffffffffu, acc[j], 1);
            acc[j] += __shfl_xor_sync(0xffffffffu, acc[j], 2);
        }
        if (c == 0){
            const float s = ss2[r128];
            #pragma unroll
            for (int j = 0; j < 8; j++) sEF[j * 128 + r128] = s * acc[j];
        }
    }
    __syncthreads();

    // ---- P7: diag (bf16 W3): sp[row] = (1-f^2) * (W3[row,:] . EF[j(row),:]) ----
    {
        const int row = tid, j = row >> 6;
        const float* Ej = sEF + j * 128;
        float a0 = 0.f, a1 = 0.f;
        #pragma unroll 4
        for (int q8 = 0; q8 < 16; q8++){
            uint4 w = W3B[q8 * 512 + row];
            float4 ea = *(const float4*)(Ej + 8 * q8);
            float4 eb = *(const float4*)(Ej + 8 * q8 + 4);
            bf8_fma(a0, a1, w, ea, eb);
        }
        float f = sf[row];
        sp[row] = (1.0f - f * f) * (a0 + a1);    // sp aliases VpT (dead)
    }
    __syncthreads();

    // ---- P8: combine + Heun update (+ readout partials in PH2) ----
    if (tid < 64){
        float acc = 0.f;
        #pragma unroll
        for (int j = 0; j < 8; j++) acc += sp[j * 64 + tid];
        #pragma unroll
        for (int i = 0; i < 8; i++) acc += gvec[i] * sf[i * 64 + tid];
        if (PH == 1){
            sm[OFF_K1 + tid] = acc;
            sm[OFF_YMID + tid] = sm[OFF_Y + tid] + dt * acc;
        } else {
            float yn = sm[OFF_Y + tid] + 0.5f * dt * (sm[OFF_K1 + tid] + acc);
            sm[OFF_Y + tid] = yn;
            readout_partial(tid, yn);
        }
    }
    __syncthreads();
}

__global__ void __launch_bounds__(NTH, 1) ncde_kernel(
    const float* __restrict__ cv,
    const float* __restrict__ Wi1, const float* __restrict__ bi1,
    const float* __restrict__ Wi2, const float* __restrict__ bi2,
    const float* __restrict__ W1, const float* __restrict__ b1,
    const float* __restrict__ W2, const float* __restrict__ b2,
    const float* __restrict__ W3, const float* __restrict__ b3,
    const float* __restrict__ Wr, const float* __restrict__ br,
    const float* __restrict__ shiftp,
    float* __restrict__ out)
{
    const int tid = threadIdx.x;
    const int b = blockIdx.x;

    const float dt = (float)WINW / (float)(LD - 1);
    const float inv_dt = 1.0f / dt;

    ulonglong2* W1Q = (ulonglong2*)(sm + OFF_W1Q);
    uint4* W2B = (uint4*)(sm + OFF_W2B);
    uint4* W3B = (uint4*)(sm + OFF_W3B);
    float* sG = sm + OFF_G;
    float* sInc = sm + OFF_W3B;   // staging inside W3B region (consumed before W3B load)

    // ---- Phase A: pack W1 (fp32 quads), W2 (bf16), increments, small params ----
    for (int idx = tid; idx < 16 * 128; idx += NTH){
        int b4 = idx >> 7, r = idx & 127;
        float4 v = ((const float4*)W1)[r * 16 + b4];
        ulonglong2 q; q.x = f2u(v.x, v.y); q.y = f2u(v.z, v.w);
        W1Q[idx] = q;
    }
    for (int idx = tid; idx < 16 * 128; idx += NTH){
        int r8 = idx >> 7, k = idx & 127;
        float4 a = ((const float4*)W2)[k * 32 + 2 * r8];
        float4 c4 = ((const float4*)W2)[k * 32 + 2 * r8 + 1];
        uint4 w;
        w.x = pk_bf16(a.x, a.y);  w.y = pk_bf16(a.z, a.w);
        w.z = pk_bf16(c4.x, c4.y); w.w = pk_bf16(c4.z, c4.w);
        W2B[idx] = w;
    }
    const float* cvb = cv + (size_t)b * LD * DD;
    for (int idx = tid; idx < 512 * 8; idx += NTH){
        sInc[idx] = cvb[idx + 8] - cvb[idx];
    }
    if (tid < 128) sm[OFF_B1 + tid] = b1[tid];
    else if (tid < 256) sm[OFF_B2 + tid - 128] = b2[tid - 128];
    if (tid < 256) sm[OFF_WR + tid] = Wr[tid];
    if (tid >= 256 && tid < 256 + 4) sm[OFF_BR + tid - 256] = br[tid - 256];
    if (tid == 300) sm[OFF_SHIFT] = *shiftp;
    for (int idx = tid; idx < 512; idx += NTH) sm[OFF_B3 + idx] = b3[idx];
    __syncthreads();

    // ---- Phase B: window log-signatures (pre-divided by dt) + y0 layer 1 ----
    for (int idx = tid; idx < NW * NPAIR; idx += NTH){
        int w = idx / NPAIR, p = idx % NPAIR;
        int i = PI_[p], j = PJ_[p];
        float acc = 0.f, pi = 0.f, pj = 0.f;
        const float* base = sInc + w * 16 * 8;
        #pragma unroll
        for (int s = 0; s < 16; s++){
            float ii = base[s * 8 + i], jj = base[s * 8 + j];
            acc += pi * jj - pj * ii;
            pi += ii; pj += jj;
        }
        sG[w * 36 + 8 + p] = 0.5f * acc * inv_dt;
    }
    for (int idx = tid; idx < NW * 8; idx += NTH){
        int w = idx >> 3, d2 = idx & 7;
        sG[w * 36 + d2] = (cvb[(16 * w + 16) * 8 + d2] - cvb[16 * w * 8 + d2]) * inv_dt;
    }
    if (tid < 64){
        float acc = bi1[tid];
        #pragma unroll
        for (int d2 = 0; d2 < 8; d2++) acc += Wi1[tid * 8 + d2] * cvb[d2];
        float dd; sm[OFF_H1 + tid] = lipswish(acc, &dd);
    }
    __syncthreads();

    // ---- Phase C: pack W3 (bf16, overwrites sInc) + y0 layer 2 ----
    for (int idx = tid; idx < 16 * 512; idx += NTH){
        int q8 = idx >> 9, row = idx & 511;
        float4 a = ((const float4*)W3)[row * 32 + 2 * q8];
        float4 c4 = ((const float4*)W3)[row * 32 + 2 * q8 + 1];
        uint4 w;
        w.x = pk_bf16(a.x, a.y);  w.y = pk_bf16(a.z, a.w);
        w.z = pk_bf16(c4.x, c4.y); w.w = pk_bf16(c4.z, c4.w);
        W3B[idx] = w;
    }
    if (tid < 64){
        float acc = bi2[tid];
        #pragma unroll 8
        for (int h = 0; h < 64; h++) acc += Wi2[tid * 64 + h] * sm[OFF_H1 + h];
        sm[OFF_Y + tid] = acc;
    }
    __syncthreads();

    // ---- Phase D: readout partials for y0 ----
    if (tid < 64) readout_partial(tid, sm[OFF_Y + tid]);
    __syncthreads();

    // ---- main Heun loop ----
    for (int n = 0; n < NW; n++){
        const float* gvec = sG + n * 36;
        // window top: cmat + write out row n (from sRO of y_n)
        if (tid < 64){
            int i = tid >> 3, j = tid & 7;
            float v = 0.0f;
            if (i < j) v = gvec[8 + pidx(i, j)];
            else if (i > j) v = -gvec[8 + pidx(j, i)];
            sm[OFF_CM + tid] = v;
        }
        if (tid >= 64 && tid < 68){
            int o = tid - 64;
            out[b * (NW + 1) * OUTD + n * OUTD + o] =
                sm[OFF_RO + o] + sm[OFF_RO + 4 + o] + sm[OFF_BR + o] + sm[OFF_SHIFT];
        }
        __syncthreads();

        vf_apply<1>(tid, sm + OFF_Y,    gvec, dt);
        vf_apply<2>(tid, sm + OFF_YMID, gvec, dt);
    }

    // final readout row NW
    if (tid < 4){
        out[b * (NW + 1) * OUTD + NW * OUTD + tid] =
            sm[OFF_RO + tid] + sm[OFF_RO + 4 + tid] + sm[OFF_BR + tid] + sm[OFF_SHIFT];
    }
}

extern "C" void kernel_launch(void* const* d_in, const int* in_sizes, int n_in,
                              void* d_out, int out_size) {
    (void)in_sizes; (void)n_in; (void)out_size;
    const size_t smem = SMEM_FLOATS * sizeof(float);  // 220,736 B
    cudaFuncSetAttribute(ncde_kernel, cudaFuncAttributeMaxDynamicSharedMemorySize, (int)smem);
    ncde_kernel<<<BD, NTH, smem>>>(
        (const float*)d_in[0],
        (const float*)d_in[1], (const float*)d_in[2],
        (const float*)d_in[3], (const float*)d_in[4],
        (const float*)d_in[5], (const float*)d_in[6],
        (const float*)d_in[7], (const float*)d_in[8],
        (const float*)d_in[9], (const float*)d_in[10],
        (const float*)d_in[11], (const float*)d_in[12],
        (const float*)d_in[13],
        (float*)d_out);
}

// round 6
// speedup vs baseline: 2.8128x; 2.8128x over previous
#include <cuda_runtime.h>

typedef unsigned long long u64;
typedef unsigned int u32;

#define BD   32
#define LD   513
#define DD   8
#define HD   64
#define WINW 16
#define NW   32
#define OUTD 4
#define NPAIR 28
#define NTH  512

// ---- smem layout (float offsets; all 16B-aligned) ----
#define OFF_W1B  0        // uint4[8*128]  bf16: W1B[b8*128+r]  = bf16(W1[r][8b8..+7])
#define OFF_W2B  4096     // uint4[16*128] bf16: W2B[r8*128+k]  = bf16(W2[k][8r8..+7])
#define OFF_W3B  12288    // uint4[16*512] bf16: W3B[q8*512+row]= bf16(W3[row][8q8..+7])
#define OFF_G    45056    // 1152
#define OFF_Y    46208
#define OFF_YMID 46272
#define OFF_K1   46336
#define OFF_CM   46400
#define OFF_H1   46464
#define OFF_S1   46592
#define OFF_H2   46720
#define OFF_S2   46848
#define OFF_F    46976    // 512
#define OFF_TP   47488    // 512
#define OFF_VPT  48000    // 512 (sp aliases: VpT dead after U1', sp born at diag)
#define OFF_SP   48000
#define OFF_D1F  48512    // 1024
#define OFF_PART 49536    // 4096 (sEF aliases chunk 0; sInc staging at init)
#define OFF_B1   53632    // 128
#define OFF_B2   53760    // 128
#define OFF_B3   53888    // 512
#define OFF_WR   54400    // 256
#define OFF_BR   54656    // 4
#define OFF_SHIFT 54660
#define SMEM_FLOATS 54664 // 218,656 B

__device__ const signed char PI_[NPAIR] = {0,0,0,0,0,0,0, 1,1,1,1,1,1, 2,2,2,2,2, 3,3,3,3, 4,4,4, 5,5, 6};
__device__ const signed char PJ_[NPAIR] = {1,2,3,4,5,6,7, 2,3,4,5,6,7, 3,4,5,6,7, 4,5,6,7, 5,6,7, 6,7, 7};

// ---------- fast math ----------
__device__ __forceinline__ float ex2f(float x){ float y; asm("ex2.approx.f32 %0, %1;" : "=f"(y) : "f"(x)); return y; }
__device__ __forceinline__ float rcpf(float x){ float y; asm("rcp.approx.f32 %0, %1;" : "=f"(y) : "f"(x)); return y; }
__device__ __forceinline__ float sigf(float x){ return rcpf(1.0f + ex2f(-1.4426950408889634f * x)); }
__device__ __forceinline__ float tanh_fast(float x){
    float t = ex2f(2.8853900817779268f * x);
    return 1.0f - 2.0f * rcpf(t + 1.0f);
}
__device__ __forceinline__ float lipswish(float x, float* dout){
    float s = sigf(x);
    *dout = 0.909f * s * fmaf(x, 1.0f - s, 1.0f);
    return 0.909f * x * s;
}

// ---------- bf16 ----------
__device__ __forceinline__ u32 pk_bf16(float lo, float hi){
    u32 r; asm("cvt.rn.bf16x2.f32 %0, %1, %2;" : "=r"(r) : "f"(hi), "f"(lo)); return r;
}
__device__ __forceinline__ float lo2f(u32 w){ return __uint_as_float(w << 16); }
__device__ __forceinline__ float hi2f(u32 w){ return __uint_as_float(w & 0xffff0000u); }

// 8 bf16 weights (uint4) dot 8 fp32 (two float4) into two accumulators
__device__ __forceinline__ void bf8_fma(float& a0, float& a1, uint4 w, float4 ha, float4 hb){
    a0 = fmaf(lo2f(w.x), ha.x, a0); a1 = fmaf(hi2f(w.x), ha.y, a1);
    a0 = fmaf(lo2f(w.y), ha.z, a0); a1 = fmaf(hi2f(w.y), ha.w, a1);
    a0 = fmaf(lo2f(w.z), hb.x, a0); a1 = fmaf(hi2f(w.z), hb.y, a1);
    a0 = fmaf(lo2f(w.w), hb.z, a0); a1 = fmaf(hi2f(w.w), hb.w, a1);
}

__device__ __forceinline__ int pidx(int i, int j) { return (i * (13 - i)) / 2 + j - 1; }

extern __shared__ float sm[];

// PH=1: writes sk1, symid.  PH=2: updates sy.
template<int PH>
__device__ __forceinline__ void vf_apply(int tid, const float* __restrict__ yv,
                                         const float* __restrict__ gvec, float dt)
{
    const uint4* W1B = (const uint4*)(sm + OFF_W1B);
    const uint4* W2B = (const uint4*)(sm + OFF_W2B);
    const uint4* W3B = (const uint4*)(sm + OFF_W3B);
    float* sh1 = sm + OFF_H1;  float* ss1 = sm + OFF_S1;
    float* sh2 = sm + OFF_H2;  float* ss2 = sm + OFF_S2;
    float* sf  = sm + OFF_F;   float* stp = sm + OFF_TP;
    float* sVpT = sm + OFF_VPT; float* sD1F = sm + OFF_D1F;
    float* sEF = sm + OFF_PART; float* sp = sm + OFF_SP;
    float* sPart = sm + OFF_PART;
    const float* scm = sm + OFF_CM;

    // ---- P1: L1 forward (128 threads) ----
    if (tid < 128) {
        const int r = tid;
        float a0 = 0.f, a1 = 0.f;
        #pragma unroll
        for (int b8 = 0; b8 < 8; b8++){
            uint4 w = W1B[b8 * 128 + r];
            float4 ya = *(const float4*)(yv + 8 * b8);
            float4 yb = *(const float4*)(yv + 8 * b8 + 4);
            bf8_fma(a0, a1, w, ya, yb);
        }
        float d; sh1[r] = lipswish(sm[OFF_B1 + r] + a0 + a1, &d); ss1[r] = d;
    }
    __syncthreads();

    // ---- P2: L2 forward (128 threads) ----
    if (tid < 128) {
        const int k = tid;
        float a0 = 0.f, a1 = 0.f;
        #pragma unroll 4
        for (int r8 = 0; r8 < 16; r8++){
            uint4 w = W2B[r8 * 128 + k];
            float4 ha = *(const float4*)(sh1 + 8 * r8);
            float4 hb = *(const float4*)(sh1 + 8 * r8 + 4);
            bf8_fma(a0, a1, w, ha, hb);
        }
        float d; sh2[k] = lipswish(sm[OFF_B2 + k] + a0 + a1, &d); ss2[k] = d;
    }
    __syncthreads();

    // ---- P3: L3 forward (512 threads, row = tid, full K=128) ----
    {
        const int row = tid;
        float a0 = 0.f, a1 = 0.f;
        #pragma unroll 4
        for (int q8 = 0; q8 < 16; q8++){
            uint4 w = W3B[q8 * 512 + row];
            float4 ha = *(const float4*)(sh2 + 8 * q8);
            float4 hb = *(const float4*)(sh2 + 8 * q8 + 4);
            bf8_fma(a0, a1, w, ha, hb);
        }
        float f = tanh_fast(sm[OFF_B3 + row] + a0 + a1);
        sf[row] = f;
        stp[row] = 1.0f - f * f;
    }
    __syncthreads();

    // ---- P4: VpT[j][b] = sum_i f[i*64+b] * cmat[i][j] ----
    {
        const int j = tid >> 6, bq = tid & 63;
        float acc = 0.f;
        #pragma unroll
        for (int i = 0; i < 8; i++) acc += sf[i * 64 + bq] * scm[i * 8 + j];
        sVpT[j * 64 + bq] = acc;
    }
    __syncthreads();

    // ---- P5: U1' partial (512 threads; c = chunk over b, r = tid&127) ----
    {
        const int c = tid >> 7, r = tid & 127;
        float acc[8] = {0,0,0,0,0,0,0,0};
        #pragma unroll
        for (int ib = 0; ib < 2; ib++){
            const int b8 = 2 * c + ib;
            uint4 w = W1B[b8 * 128 + r];
            float w0 = lo2f(w.x), w1 = hi2f(w.x), w2 = lo2f(w.y), w3 = hi2f(w.y);
            float w4 = lo2f(w.z), w5 = hi2f(w.z), w6 = lo2f(w.w), w7 = hi2f(w.w);
            #pragma unroll
            for (int j = 0; j < 8; j++){
                float4 d0 = *(const float4*)(sVpT + j * 64 + 8 * b8);
                float4 d1 = *(const float4*)(sVpT + j * 64 + 8 * b8 + 4);
                float t = acc[j];
                t = fmaf(w0, d0.x, t); t = fmaf(w1, d0.y, t);
                t = fmaf(w2, d0.z, t); t = fmaf(w3, d0.w, t);
                t = fmaf(w4, d1.x, t); t = fmaf(w5, d1.y, t);
                t = fmaf(w6, d1.z, t); t = fmaf(w7, d1.w, t);
                acc[j] = t;
            }
        }
        #pragma unroll
        for (int j = 0; j < 8; j++) sPart[c * 1024 + j * 128 + r] = acc[j];
    }
    __syncthreads();

    // ---- P5b: U1' reduce -> D1F[j][r] ----
    {
        const int j = tid >> 7, r = tid & 127;
        const float s = ss1[r];
        #pragma unroll
        for (int jj = j; jj < 8; jj += 4){
            float v = sPart[jj * 128 + r] + sPart[1024 + jj * 128 + r]
                    + sPart[2048 + jj * 128 + r] + sPart[3072 + jj * 128 + r];
            sD1F[jj * 128 + r] = s * v;
        }
    }
    __syncthreads();

    // ---- P6: U2' partial (512 threads; c = chunk over r, k = tid&127) ----
    {
        const int c = tid >> 7, k = tid & 127;
        float acc[8] = {0,0,0,0,0,0,0,0};
        #pragma unroll
        for (int ir = 0; ir < 4; ir++){
            const int r8 = 4 * c + ir;
            uint4 w = W2B[r8 * 128 + k];
            float w0 = lo2f(w.x), w1 = hi2f(w.x), w2 = lo2f(w.y), w3 = hi2f(w.y);
            float w4 = lo2f(w.z), w5 = hi2f(w.z), w6 = lo2f(w.w), w7 = hi2f(w.w);
            #pragma unroll
            for (int j = 0; j < 8; j++){
                float4 d0 = *(const float4*)(sD1F + j * 128 + 8 * r8);
                float4 d1 = *(const float4*)(sD1F + j * 128 + 8 * r8 + 4);
                float t = acc[j];
                t = fmaf(w0, d0.x, t); t = fmaf(w1, d0.y, t);
                t = fmaf(w2, d0.z, t); t = fmaf(w3, d0.w, t);
                t = fmaf(w4, d1.x, t); t = fmaf(w5, d1.y, t);
                t = fmaf(w6, d1.z, t); t = fmaf(w7, d1.w, t);
                acc[j] = t;
            }
        }
        #pragma unroll
        for (int j = 0; j < 8; j++) sPart[c * 1024 + j * 128 + k] = acc[j];
    }
    __syncthreads();

    // ---- P6b: U2' reduce -> EF[j][k] (sEF aliases sPart chunk 0) ----
    {
        const int j = tid >> 7, k = tid & 127;
        const float s = ss2[k];
        #pragma unroll
        for (int jj = j; jj < 8; jj += 4){
            float v = sPart[jj * 128 + k] + sPart[1024 + jj * 128 + k]
                    + sPart[2048 + jj * 128 + k] + sPart[3072 + jj * 128 + k];
            sEF[jj * 128 + k] = s * v;
        }
    }
    __syncthreads();

    // ---- P7: diag (row = tid, j = row>>6, full K=128) ----
    {
        const int row = tid, j = row >> 6;
        const float* Ej = sEF + j * 128;
        float a0 = 0.f, a1 = 0.f;
        #pragma unroll 4
        for (int q8 = 0; q8 < 16; q8++){
            uint4 w = W3B[q8 * 512 + row];
            float4 ea = *(const float4*)(Ej + 8 * q8);
            float4 eb = *(const float4*)(Ej + 8 * q8 + 4);
            bf8_fma(a0, a1, w, ea, eb);
        }
        sp[row] = stp[row] * (a0 + a1);   // sp aliases VpT (dead)
    }
    __syncthreads();

    // ---- P8: combine + Heun update ----
    if (tid < 64){
        float acc = 0.f;
        #pragma unroll
        for (int j = 0; j < 8; j++) acc += sp[j * 64 + tid];
        #pragma unroll
        for (int i = 0; i < 8; i++) acc += gvec[i] * sf[i * 64 + tid];
        if (PH == 1){
            sm[OFF_K1 + tid] = acc;
            sm[OFF_YMID + tid] = sm[OFF_Y + tid] + dt * acc;
        } else {
            sm[OFF_Y + tid] = sm[OFF_Y + tid] + 0.5f * dt * (sm[OFF_K1 + tid] + acc);
        }
    }
    __syncthreads();
}

__global__ void __launch_bounds__(NTH, 1) ncde_kernel(
    const float* __restrict__ cv,
    const float* __restrict__ Wi1, const float* __restrict__ bi1,
    const float* __restrict__ Wi2, const float* __restrict__ bi2,
    const float* __restrict__ W1, const float* __restrict__ b1,
    const float* __restrict__ W2, const float* __restrict__ b2,
    const float* __restrict__ W3, const float* __restrict__ b3,
    const float* __restrict__ Wr, const float* __restrict__ br,
    const float* __restrict__ shiftp,
    float* __restrict__ out)
{
    const int tid = threadIdx.x;
    const int b = blockIdx.x;

    const float dt = (float)WINW / (float)(LD - 1);
    const float inv_dt = 1.0f / dt;

    uint4* W1B = (uint4*)(sm + OFF_W1B);
    uint4* W2B = (uint4*)(sm + OFF_W2B);
    uint4* W3B = (uint4*)(sm + OFF_W3B);
    float* sG = sm + OFF_G;
    float* sInc = sm + OFF_PART;  // staging (4096 floats)

    // ---- init: pack weights bf16, load increments + small params ----
    for (int idx = tid; idx < 8 * 128; idx += NTH){
        int b8 = idx >> 7, r = idx & 127;
        float4 a = ((const float4*)W1)[r * 16 + 2 * b8];
        float4 c4 = ((const float4*)W1)[r * 16 + 2 * b8 + 1];
        uint4 w;
        w.x = pk_bf16(a.x, a.y);   w.y = pk_bf16(a.z, a.w);
        w.z = pk_bf16(c4.x, c4.y); w.w = pk_bf16(c4.z, c4.w);
        W1B[idx] = w;
    }
    for (int idx = tid; idx < 16 * 128; idx += NTH){
        int r8 = idx >> 7, k = idx & 127;
        float4 a = ((const float4*)W2)[k * 32 + 2 * r8];
        float4 c4 = ((const float4*)W2)[k * 32 + 2 * r8 + 1];
        uint4 w;
        w.x = pk_bf16(a.x, a.y);   w.y = pk_bf16(a.z, a.w);
        w.z = pk_bf16(c4.x, c4.y); w.w = pk_bf16(c4.z, c4.w);
        W2B[idx] = w;
    }
    for (int idx = tid; idx < 16 * 512; idx += NTH){
        int q8 = idx >> 9, row = idx & 511;
        float4 a = ((const float4*)W3)[row * 32 + 2 * q8];
        float4 c4 = ((const float4*)W3)[row * 32 + 2 * q8 + 1];
        uint4 w;
        w.x = pk_bf16(a.x, a.y);   w.y = pk_bf16(a.z, a.w);
        w.z = pk_bf16(c4.x, c4.y); w.w = pk_bf16(c4.z, c4.w);
        W3B[idx] = w;
    }
    const float* cvb = cv + (size_t)b * LD * DD;
    for (int idx = tid; idx < 512 * 8; idx += NTH){
        sInc[idx] = cvb[idx + 8] - cvb[idx];
    }
    if (tid < 128) sm[OFF_B1 + tid] = b1[tid];
    else if (tid < 256) sm[OFF_B2 + tid - 128] = b2[tid - 128];
    else if (tid < 260) sm[OFF_BR + tid - 256] = br[tid - 256];
    else if (tid == 260) sm[OFF_SHIFT] = *shiftp;
    if (tid >= 261 && tid < 261 + 128) {
        // nothing (keep simple)
    }
    for (int idx = tid; idx < 512; idx += NTH) sm[OFF_B3 + idx] = b3[idx];
    for (int idx = tid; idx < 256; idx += NTH) sm[OFF_WR + idx] = Wr[idx];
    __syncthreads();

    // ---- window log-signatures (pre-divided by dt) + y0 layer 1 ----
    for (int idx = tid; idx < NW * NPAIR; idx += NTH){
        int w = idx / NPAIR, p = idx % NPAIR;
        int i = PI_[p], j = PJ_[p];
        float acc = 0.f, pi = 0.f, pj = 0.f;
        const float* base = sInc + w * 16 * 8;
        #pragma unroll
        for (int s = 0; s < 16; s++){
            float ii = base[s * 8 + i], jj = base[s * 8 + j];
            acc += pi * jj - pj * ii;
            pi += ii; pj += jj;
        }
        sG[w * 36 + 8 + p] = 0.5f * acc * inv_dt;
    }
    for (int idx = tid; idx < NW * 8; idx += NTH){
        int w = idx >> 3, d2 = idx & 7;
        sG[w * 36 + d2] = (cvb[(16 * w + 16) * 8 + d2] - cvb[16 * w * 8 + d2]) * inv_dt;
    }
    if (tid < 64){
        float acc = bi1[tid];
        #pragma unroll
        for (int d2 = 0; d2 < 8; d2++) acc += Wi1[tid * 8 + d2] * cvb[d2];
        float dd; sm[OFF_H1 + tid] = lipswish(acc, &dd);
    }
    __syncthreads();
    if (tid < 64){
        float acc = bi2[tid];
        #pragma unroll 8
        for (int h = 0; h < 64; h++) acc += Wi2[tid * 64 + h] * sm[OFF_H1 + h];
        sm[OFF_Y + tid] = acc;
    }
    __syncthreads();

    // ---- main Heun loop ----
    for (int n = 0; n < NW; n++){
        const float* gvec = sG + n * 36;
        if (tid < 64){
            int i = tid >> 3, j = tid & 7;
            float v = 0.0f;
            if (i < j) v = gvec[8 + pidx(i, j)];
            else if (i > j) v = -gvec[8 + pidx(j, i)];
            sm[OFF_CM + tid] = v;
        } else if (tid < 68){
            int o = tid - 64;
            float acc = sm[OFF_BR + o] + sm[OFF_SHIFT];
            #pragma unroll 8
            for (int a = 0; a < 64; a++) acc += sm[OFF_WR + o * 64 + a] * sm[OFF_Y + a];
            out[b * (NW + 1) * OUTD + n * OUTD + o] = acc;
        }
        __syncthreads();

        vf_apply<1>(tid, sm + OFF_Y,    gvec, dt);
        vf_apply<2>(tid, sm + OFF_YMID, gvec, dt);
    }

    // final readout (index NW)
    if (tid < 4){
        float acc = sm[OFF_BR + tid] + sm[OFF_SHIFT];
        #pragma unroll 8
        for (int a = 0; a < 64; a++) acc += sm[OFF_WR + tid * 64 + a] * sm[OFF_Y + a];
        out[b * (NW + 1) * OUTD + NW * OUTD + tid] = acc;
    }
}

extern "C" void kernel_launch(void* const* d_in, const int* in_sizes, int n_in,
                              void* d_out, int out_size) {
    (void)in_sizes; (void)n_in; (void)out_size;
    const size_t smem = SMEM_FLOATS * sizeof(float);  // 218,656 B
    cudaFuncSetAttribute(ncde_kernel, cudaFuncAttributeMaxDynamicSharedMemorySize, (int)smem);
    ncde_kernel<<<BD, NTH, smem>>>(
        (const float*)d_in[0],
        (const float*)d_in[1], (const float*)d_in[2],
        (const float*)d_in[3], (const float*)d_in[4],
        (const float*)d_in[5], (const float*)d_in[6],
        (const float*)d_in[7], (const float*)d_in[8],
        (const float*)d_in[9], (const float*)d_in[10],
        (const float*)d_in[11], (const float*)d_in[12],
        (const float*)d_in[13],
        (float*)d_out);
}